// round 1
// baseline (speedup 1.0000x reference)
#include <cuda_runtime.h>
#include <math.h>

#define N_NODES 40962
#define N_EDGES 245760
#define KG 10
#define GMM_EPS 1e-15f

// ---------------- scratch (device globals; no runtime allocation) -------------
__device__ float d_z1[(size_t)N_NODES * 640];    // x @ g1        [N, K*64]
__device__ float d_z2[(size_t)N_NODES * 1280];   // h @ g2        [N, K*128]
__device__ float d_zs[(size_t)N_NODES * 1280];   // x @ gs        [N, K*128]
__device__ float d_h [(size_t)N_NODES * 64];     // hidden after relu
__device__ float d_r1[(size_t)N_NODES * 64];     // x @ root1
__device__ float d_r2[(size_t)N_NODES * 128];    // h @ root2 + x @ roots
__device__ float d_agg1[(size_t)N_NODES * 64];   // scatter sum conv1
__device__ float d_agg2[(size_t)N_NODES * 128];  // scatter sum conv2 + shortcut
__device__ float d_deg[N_NODES];

// ---------------- zero scratch accumulators ----------------------------------
__global__ void zero_bufs() {
    size_t idx = (size_t)blockIdx.x * blockDim.x + threadIdx.x;
    size_t t1 = (size_t)N_NODES * 64;
    size_t t2 = (size_t)N_NODES * 128;
    if (idx < t2) d_agg2[idx] = 0.0f;
    if (idx < t1) d_agg1[idx] = 0.0f;
    if (idx < (size_t)N_NODES) d_deg[idx] = 0.0f;
}

// ---------------- SGEMM, K fixed at 64, fp32 ---------------------------------
// C[M,N] = A[M,64] @ B[64,N]  (+= if accumulate). BM=BN=64, 256 thr, 4x4/thread.
__global__ __launch_bounds__(256) void sgemm_k64(
    const float* __restrict__ A, const float* __restrict__ B,
    float* __restrict__ C, int M, int N, int accumulate)
{
    __shared__ float As[64][68];   // [k][m] (transposed A tile)
    __shared__ float Bs[64][68];   // [k][n]
    const int tid = threadIdx.x;
    const int bm = blockIdx.y * 64;
    const int bn = blockIdx.x * 64;

    // load A tile (transpose into As)
    {
        int row = tid >> 2;
        int kq  = (tid & 3) * 16;
        const float* ap = A + (size_t)(bm + row) * 64 + kq;
        bool valid = (bm + row) < M;
        #pragma unroll
        for (int j = 0; j < 4; ++j) {
            float4 v = valid ? *(const float4*)(ap + 4 * j) : make_float4(0.f, 0.f, 0.f, 0.f);
            As[kq + 4 * j + 0][row] = v.x;
            As[kq + 4 * j + 1][row] = v.y;
            As[kq + 4 * j + 2][row] = v.z;
            As[kq + 4 * j + 3][row] = v.w;
        }
    }
    // load B tile
    {
        int k  = tid >> 2;
        int nq = (tid & 3) * 16;
        const float* bp = B + (size_t)k * N + bn + nq;
        #pragma unroll
        for (int j = 0; j < 4; ++j) {
            float4 v = *(const float4*)(bp + 4 * j);
            *(float4*)&Bs[k][nq + 4 * j] = v;
        }
    }
    __syncthreads();

    const int tx = tid & 15;
    const int ty = tid >> 4;
    float acc[4][4] = {};
    #pragma unroll 8
    for (int k = 0; k < 64; ++k) {
        float4 a = *(const float4*)&As[k][ty * 4];
        float4 b = *(const float4*)&Bs[k][tx * 4];
        float av[4] = {a.x, a.y, a.z, a.w};
        float bv[4] = {b.x, b.y, b.z, b.w};
        #pragma unroll
        for (int i = 0; i < 4; ++i)
            #pragma unroll
            for (int j = 0; j < 4; ++j)
                acc[i][j] = fmaf(av[i], bv[j], acc[i][j]);
    }

    #pragma unroll
    for (int i = 0; i < 4; ++i) {
        int row = bm + ty * 4 + i;
        if (row < M) {
            float* cp = C + (size_t)row * N + bn + tx * 4;
            float4 v = make_float4(acc[i][0], acc[i][1], acc[i][2], acc[i][3]);
            if (accumulate) {
                float4 o = *(const float4*)cp;
                v.x += o.x; v.y += o.y; v.z += o.z; v.w += o.w;
            }
            *(float4*)cp = v;
        }
    }
}

// ---------------- edge pass 1: conv1 scatter (Ch=64) + degree -----------------
// one warp per edge; lanes 0..9 compute gaussian weights, broadcast via shfl.
__global__ __launch_bounds__(256) void edge_pass1(
    const int* __restrict__ ei, const float* __restrict__ pseudo,
    const float* __restrict__ mu, const float* __restrict__ sigma)
{
    int gtid = blockIdx.x * blockDim.x + threadIdx.x;
    int e = gtid >> 5;
    int lane = gtid & 31;
    if (e >= N_EDGES) return;
    int src = ei[e];
    int dst = ei[N_EDGES + e];
    float p0 = pseudo[2 * e], p1 = pseudo[2 * e + 1];

    float wv = 0.0f;
    if (lane < KG) {
        float m0 = mu[2 * lane], m1 = mu[2 * lane + 1];
        float s0 = sigma[2 * lane], s1 = sigma[2 * lane + 1];
        float dx = p0 - m0, dy = p1 - m1;
        float ex = -0.5f * dx * dx / (GMM_EPS + s0 * s0)
                 - 0.5f * dy * dy / (GMM_EPS + s1 * s1);
        wv = __expf(ex);
    }

    const float* zr = d_z1 + (size_t)src * 640;
    float a0 = 0.f, a1 = 0.f;
    #pragma unroll
    for (int k = 0; k < KG; ++k) {
        float w = __shfl_sync(0xffffffffu, wv, k);
        a0 = fmaf(w, zr[k * 64 + lane], a0);
        a1 = fmaf(w, zr[k * 64 + 32 + lane], a1);
    }
    atomicAdd(&d_agg1[(size_t)dst * 64 + lane], a0);
    atomicAdd(&d_agg1[(size_t)dst * 64 + 32 + lane], a1);
    if (lane == 0) atomicAdd(&d_deg[dst], 1.0f);
}

// ---------------- edge pass 2: conv2 + shortcut fused (Cout=128) --------------
__global__ __launch_bounds__(256) void edge_pass2(
    const int* __restrict__ ei, const float* __restrict__ pseudo,
    const float* __restrict__ mu2, const float* __restrict__ sigma2,
    const float* __restrict__ mus, const float* __restrict__ sigmas)
{
    int gtid = blockIdx.x * blockDim.x + threadIdx.x;
    int e = gtid >> 5;
    int lane = gtid & 31;
    if (e >= N_EDGES) return;
    int src = ei[e];
    int dst = ei[N_EDGES + e];
    float p0 = pseudo[2 * e], p1 = pseudo[2 * e + 1];

    float wv = 0.0f;
    if (lane < KG) {
        float m0 = mu2[2 * lane], m1 = mu2[2 * lane + 1];
        float s0 = sigma2[2 * lane], s1 = sigma2[2 * lane + 1];
        float dx = p0 - m0, dy = p1 - m1;
        wv = __expf(-0.5f * dx * dx / (GMM_EPS + s0 * s0)
                    - 0.5f * dy * dy / (GMM_EPS + s1 * s1));
    } else if (lane < 2 * KG) {
        int k = lane - KG;
        float m0 = mus[2 * k], m1 = mus[2 * k + 1];
        float s0 = sigmas[2 * k], s1 = sigmas[2 * k + 1];
        float dx = p0 - m0, dy = p1 - m1;
        wv = __expf(-0.5f * dx * dx / (GMM_EPS + s0 * s0)
                    - 0.5f * dy * dy / (GMM_EPS + s1 * s1));
    }

    const float* z2r = d_z2 + (size_t)src * 1280;
    const float* zsr = d_zs + (size_t)src * 1280;
    float acc[4] = {0.f, 0.f, 0.f, 0.f};
    #pragma unroll
    for (int k = 0; k < KG; ++k) {
        float w2 = __shfl_sync(0xffffffffu, wv, k);
        float ws = __shfl_sync(0xffffffffu, wv, KG + k);
        #pragma unroll
        for (int j = 0; j < 4; ++j) {
            int c = k * 128 + j * 32 + lane;
            acc[j] = fmaf(w2, z2r[c], acc[j]);
            acc[j] = fmaf(ws, zsr[c], acc[j]);
        }
    }
    #pragma unroll
    for (int j = 0; j < 4; ++j)
        atomicAdd(&d_agg2[(size_t)dst * 128 + j * 32 + lane], acc[j]);
}

// ---------------- epilogues ---------------------------------------------------
__global__ void finish1(const float* __restrict__ b1) {
    int idx = blockIdx.x * blockDim.x + threadIdx.x;
    if (idx >= N_NODES * 64) return;
    int i = idx >> 6, c = idx & 63;
    float dg = fmaxf(d_deg[i], 1.0f);
    float v = d_agg1[idx] / dg + d_r1[idx] + b1[c];
    d_h[idx] = fmaxf(v, 0.0f);
}

__global__ void finish2(const float* __restrict__ b2, const float* __restrict__ bs,
                        float* __restrict__ out) {
    int idx = blockIdx.x * blockDim.x + threadIdx.x;
    if (idx >= N_NODES * 128) return;
    int i = idx >> 7, c = idx & 127;
    float dg = fmaxf(d_deg[i], 1.0f);
    float v = d_agg2[idx] / dg + d_r2[idx] + b2[c] + bs[c];
    out[idx] = fmaxf(v, 0.0f);
}

// ---------------- launch ------------------------------------------------------
extern "C" void kernel_launch(void* const* d_in, const int* in_sizes, int n_in,
                              void* d_out, int out_size) {
    const float* x      = (const float*)d_in[0];
    const int*   ei     = (const int*)  d_in[1];
    const float* pseudo = (const float*)d_in[2];
    const float* g1     = (const float*)d_in[3];
    const float* mu1    = (const float*)d_in[4];
    const float* sigma1 = (const float*)d_in[5];
    const float* root1  = (const float*)d_in[6];
    const float* b1     = (const float*)d_in[7];
    const float* g2     = (const float*)d_in[8];
    const float* mu2    = (const float*)d_in[9];
    const float* sigma2 = (const float*)d_in[10];
    const float* root2  = (const float*)d_in[11];
    const float* b2     = (const float*)d_in[12];
    const float* gs     = (const float*)d_in[13];
    const float* mus    = (const float*)d_in[14];
    const float* sigmas = (const float*)d_in[15];
    const float* roots  = (const float*)d_in[16];
    const float* bs     = (const float*)d_in[17];
    float* out = (float*)d_out;

    float *z1p, *z2p, *zsp, *hp, *r1p, *r2p;
    cudaGetSymbolAddress((void**)&z1p, d_z1);
    cudaGetSymbolAddress((void**)&z2p, d_z2);
    cudaGetSymbolAddress((void**)&zsp, d_zs);
    cudaGetSymbolAddress((void**)&hp,  d_h);
    cudaGetSymbolAddress((void**)&r1p, d_r1);
    cudaGetSymbolAddress((void**)&r2p, d_r2);

    const int MT = (N_NODES + 63) / 64;   // 641 row tiles

    // zero accumulators
    {
        int total = N_NODES * 128;
        zero_bufs<<<(total + 255) / 256, 256>>>();
    }

    // conv1: z1 = x@g1, r1 = x@root1
    sgemm_k64<<<dim3(640 / 64, MT), 256>>>(x, g1, z1p, N_NODES, 640, 0);
    sgemm_k64<<<dim3(1, MT), 256>>>(x, root1, r1p, N_NODES, 64, 0);
    edge_pass1<<<(N_EDGES * 32) / 256, 256>>>(ei, pseudo, mu1, sigma1);
    finish1<<<(N_NODES * 64 + 255) / 256, 256>>>(b1);

    // conv2 + shortcut
    sgemm_k64<<<dim3(1280 / 64, MT), 256>>>(hp, g2, z2p, N_NODES, 1280, 0);
    sgemm_k64<<<dim3(1280 / 64, MT), 256>>>(x, gs, zsp, N_NODES, 1280, 0);
    sgemm_k64<<<dim3(128 / 64, MT), 256>>>(hp, root2, r2p, N_NODES, 128, 0);
    sgemm_k64<<<dim3(128 / 64, MT), 256>>>(x, roots, r2p, N_NODES, 128, 1);
    edge_pass2<<<(N_EDGES * 32) / 256, 256>>>(ei, pseudo, mu2, sigma2, mus, sigmas);
    finish2<<<(N_NODES * 128 + 255) / 256, 256>>>(b2, bs, out);
}

// round 2
// speedup vs baseline: 1.2406x; 1.2406x over previous
#include <cuda_runtime.h>
#include <math.h>

#define N_NODES 40962
#define N_EDGES 245760
#define KG 10
#define GMM_EPS 1e-15f

// ---------------- scratch (device globals; no runtime allocation) -------------
__device__ float d_z1[(size_t)N_NODES * 640];    // x @ g1        [N, K*64]
__device__ float d_z2[(size_t)N_NODES * 1280];   // h @ g2        [N, K*128]
__device__ float d_zs[(size_t)N_NODES * 1280];   // x @ gs        [N, K*128]
__device__ float d_h [(size_t)N_NODES * 64];     // hidden after relu
__device__ float d_r1[(size_t)N_NODES * 64];     // x @ root1
__device__ float d_r2[(size_t)N_NODES * 128];    // h @ root2 + x @ roots
__device__ float d_agg1[(size_t)N_NODES * 64];   // scatter sum conv1
__device__ float d_agg2[(size_t)N_NODES * 128];  // scatter sum conv2 + shortcut
__device__ float d_deg[N_NODES];

// ---------------- zero scratch accumulators ----------------------------------
__global__ void zero_bufs() {
    size_t idx = (size_t)blockIdx.x * blockDim.x + threadIdx.x;
    size_t t1 = (size_t)N_NODES * 64;
    size_t t2 = (size_t)N_NODES * 128;
    if (idx < t2) d_agg2[idx] = 0.0f;
    if (idx < t1) d_agg1[idx] = 0.0f;
    if (idx < (size_t)N_NODES) d_deg[idx] = 0.0f;
}

// ---------------- helpers -----------------------------------------------------
__device__ __forceinline__ unsigned f2tf32(float x) {
    unsigned r;
    asm("cvt.rna.tf32.f32 %0, %1;" : "=r"(r) : "f"(x));
    return r;
}
__device__ __forceinline__ unsigned fu(float x) { return __float_as_uint(x); }

// ---------------- tf32 tensor-core GEMM, K fixed at 64 ------------------------
// C[M,N] = A[M,64] @ B[64,N] (+= if accumulate).
// BM=BN=64, BK=64 one-shot. 256 threads = 8 warps (4 m x 2 n), 32x32 per warp,
// mma.sync.m16n8k8.tf32: 1 m-tile x 4 n-tiles x 8 k-steps per warp.
__global__ __launch_bounds__(256) void gemm_tf32(
    const float* __restrict__ A, const float* __restrict__ B,
    float* __restrict__ C, int M, int N, int accumulate)
{
    __shared__ float As[64][68];   // [row][k], stride 68 -> conflict-free frags
    __shared__ float Bs[64][72];   // [k][n],  stride 72 -> conflict-free frags

    const int tid = threadIdx.x;
    const int bm = blockIdx.y * 64;
    const int bn = blockIdx.x * 64;

    // ---- global -> smem, converting to tf32 bit patterns ----
    {
        int row = tid >> 2;             // 0..63
        int cq  = (tid & 3) * 16;       // 0,16,32,48
        bool av = (bm + row) < M;
        const float* ap = A + (size_t)(bm + row) * 64 + cq;
        #pragma unroll
        for (int j = 0; j < 4; ++j) {
            float4 v = av ? *(const float4*)(ap + 4 * j) : make_float4(0.f, 0.f, 0.f, 0.f);
            As[row][cq + 4 * j + 0] = __uint_as_float(f2tf32(v.x));
            As[row][cq + 4 * j + 1] = __uint_as_float(f2tf32(v.y));
            As[row][cq + 4 * j + 2] = __uint_as_float(f2tf32(v.z));
            As[row][cq + 4 * j + 3] = __uint_as_float(f2tf32(v.w));
        }
    }
    {
        int k  = tid >> 2;
        int nq = (tid & 3) * 16;
        const float* bp = B + (size_t)k * N + bn + nq;
        #pragma unroll
        for (int j = 0; j < 4; ++j) {
            float4 v = *(const float4*)(bp + 4 * j);
            Bs[k][nq + 4 * j + 0] = __uint_as_float(f2tf32(v.x));
            Bs[k][nq + 4 * j + 1] = __uint_as_float(f2tf32(v.y));
            Bs[k][nq + 4 * j + 2] = __uint_as_float(f2tf32(v.z));
            Bs[k][nq + 4 * j + 3] = __uint_as_float(f2tf32(v.w));
        }
    }
    __syncthreads();

    const int wid = tid >> 5;
    const int l   = tid & 31;
    const int wr  = wid & 3;      // warp m index (0..3) -> rows wr*16..+15
    const int wc  = wid >> 2;     // warp n index (0..1) -> cols wc*32..+31
    const int tg  = l >> 2;       // group id (0..7)
    const int ti  = l & 3;        // thread-in-group (0..3)

    float acc[4][4] = {};         // [n-tile][c0..c3]

    #pragma unroll
    for (int ks = 0; ks < 8; ++ks) {
        int c0 = ks * 8 + ti;
        unsigned a0 = fu(As[wr * 16 + tg    ][c0    ]);
        unsigned a1 = fu(As[wr * 16 + tg + 8][c0    ]);
        unsigned a2 = fu(As[wr * 16 + tg    ][c0 + 4]);
        unsigned a3 = fu(As[wr * 16 + tg + 8][c0 + 4]);
        #pragma unroll
        for (int nt = 0; nt < 4; ++nt) {
            int bc = wc * 32 + nt * 8 + tg;
            unsigned b0 = fu(Bs[ks * 8 + ti    ][bc]);
            unsigned b1 = fu(Bs[ks * 8 + ti + 4][bc]);
            asm volatile(
                "mma.sync.aligned.m16n8k8.row.col.f32.tf32.tf32.f32 "
                "{%0,%1,%2,%3}, {%4,%5,%6,%7}, {%8,%9}, {%0,%1,%2,%3};"
                : "+f"(acc[nt][0]), "+f"(acc[nt][1]),
                  "+f"(acc[nt][2]), "+f"(acc[nt][3])
                : "r"(a0), "r"(a1), "r"(a2), "r"(a3), "r"(b0), "r"(b1));
        }
    }

    // ---- store: thread owns cols {2*ti, 2*ti+1} of rows tg, tg+8 ----
    #pragma unroll
    for (int nt = 0; nt < 4; ++nt) {
        int col = bn + wc * 32 + nt * 8 + 2 * ti;
        int r0 = bm + wr * 16 + tg;
        int r1 = r0 + 8;
        if (r0 < M) {
            float2* cp = (float2*)(C + (size_t)r0 * N + col);
            float2 v = make_float2(acc[nt][0], acc[nt][1]);
            if (accumulate) { float2 o = *cp; v.x += o.x; v.y += o.y; }
            *cp = v;
        }
        if (r1 < M) {
            float2* cp = (float2*)(C + (size_t)r1 * N + col);
            float2 v = make_float2(acc[nt][2], acc[nt][3]);
            if (accumulate) { float2 o = *cp; v.x += o.x; v.y += o.y; }
            *cp = v;
        }
    }
}

// ---------------- edge pass 1: conv1 scatter (Ch=64) + degree -----------------
__global__ __launch_bounds__(256) void edge_pass1(
    const int* __restrict__ ei, const float* __restrict__ pseudo,
    const float* __restrict__ mu, const float* __restrict__ sigma)
{
    int gtid = blockIdx.x * blockDim.x + threadIdx.x;
    int e = gtid >> 5;
    int lane = gtid & 31;
    if (e >= N_EDGES) return;
    int src = ei[e];
    int dst = ei[N_EDGES + e];
    float p0 = pseudo[2 * e], p1 = pseudo[2 * e + 1];

    float wv = 0.0f;
    if (lane < KG) {
        float m0 = mu[2 * lane], m1 = mu[2 * lane + 1];
        float s0 = sigma[2 * lane], s1 = sigma[2 * lane + 1];
        float dx = p0 - m0, dy = p1 - m1;
        float ex = -0.5f * dx * dx / (GMM_EPS + s0 * s0)
                 - 0.5f * dy * dy / (GMM_EPS + s1 * s1);
        wv = __expf(ex);
    }

    const float* zr = d_z1 + (size_t)src * 640;
    float a0 = 0.f, a1 = 0.f;
    #pragma unroll
    for (int k = 0; k < KG; ++k) {
        float w = __shfl_sync(0xffffffffu, wv, k);
        a0 = fmaf(w, zr[k * 64 + lane], a0);
        a1 = fmaf(w, zr[k * 64 + 32 + lane], a1);
    }
    atomicAdd(&d_agg1[(size_t)dst * 64 + lane], a0);
    atomicAdd(&d_agg1[(size_t)dst * 64 + 32 + lane], a1);
    if (lane == 0) atomicAdd(&d_deg[dst], 1.0f);
}

// ---------------- edge pass 2: conv2 + shortcut fused (Cout=128) --------------
__global__ __launch_bounds__(256) void edge_pass2(
    const int* __restrict__ ei, const float* __restrict__ pseudo,
    const float* __restrict__ mu2, const float* __restrict__ sigma2,
    const float* __restrict__ mus, const float* __restrict__ sigmas)
{
    int gtid = blockIdx.x * blockDim.x + threadIdx.x;
    int e = gtid >> 5;
    int lane = gtid & 31;
    if (e >= N_EDGES) return;
    int src = ei[e];
    int dst = ei[N_EDGES + e];
    float p0 = pseudo[2 * e], p1 = pseudo[2 * e + 1];

    float wv = 0.0f;
    if (lane < KG) {
        float m0 = mu2[2 * lane], m1 = mu2[2 * lane + 1];
        float s0 = sigma2[2 * lane], s1 = sigma2[2 * lane + 1];
        float dx = p0 - m0, dy = p1 - m1;
        wv = __expf(-0.5f * dx * dx / (GMM_EPS + s0 * s0)
                    - 0.5f * dy * dy / (GMM_EPS + s1 * s1));
    } else if (lane < 2 * KG) {
        int k = lane - KG;
        float m0 = mus[2 * k], m1 = mus[2 * k + 1];
        float s0 = sigmas[2 * k], s1 = sigmas[2 * k + 1];
        float dx = p0 - m0, dy = p1 - m1;
        wv = __expf(-0.5f * dx * dx / (GMM_EPS + s0 * s0)
                    - 0.5f * dy * dy / (GMM_EPS + s1 * s1));
    }

    const float* z2r = d_z2 + (size_t)src * 1280;
    const float* zsr = d_zs + (size_t)src * 1280;
    float acc[4] = {0.f, 0.f, 0.f, 0.f};
    #pragma unroll
    for (int k = 0; k < KG; ++k) {
        float w2 = __shfl_sync(0xffffffffu, wv, k);
        float ws = __shfl_sync(0xffffffffu, wv, KG + k);
        #pragma unroll
        for (int j = 0; j < 4; ++j) {
            int c = k * 128 + j * 32 + lane;
            acc[j] = fmaf(w2, z2r[c], acc[j]);
            acc[j] = fmaf(ws, zsr[c], acc[j]);
        }
    }
    #pragma unroll
    for (int j = 0; j < 4; ++j)
        atomicAdd(&d_agg2[(size_t)dst * 128 + j * 32 + lane], acc[j]);
}

// ---------------- epilogues ---------------------------------------------------
__global__ void finish1(const float* __restrict__ b1) {
    int idx = blockIdx.x * blockDim.x + threadIdx.x;
    if (idx >= N_NODES * 64) return;
    int i = idx >> 6, c = idx & 63;
    float dg = fmaxf(d_deg[i], 1.0f);
    float v = d_agg1[idx] / dg + d_r1[idx] + b1[c];
    d_h[idx] = fmaxf(v, 0.0f);
}

__global__ void finish2(const float* __restrict__ b2, const float* __restrict__ bs,
                        float* __restrict__ out) {
    int idx = blockIdx.x * blockDim.x + threadIdx.x;
    if (idx >= N_NODES * 128) return;
    int i = idx >> 7, c = idx & 127;
    float dg = fmaxf(d_deg[i], 1.0f);
    float v = d_agg2[idx] / dg + d_r2[idx] + b2[c] + bs[c];
    out[idx] = fmaxf(v, 0.0f);
}

// ---------------- launch ------------------------------------------------------
extern "C" void kernel_launch(void* const* d_in, const int* in_sizes, int n_in,
                              void* d_out, int out_size) {
    const float* x      = (const float*)d_in[0];
    const int*   ei     = (const int*)  d_in[1];
    const float* pseudo = (const float*)d_in[2];
    const float* g1     = (const float*)d_in[3];
    const float* mu1    = (const float*)d_in[4];
    const float* sigma1 = (const float*)d_in[5];
    const float* root1  = (const float*)d_in[6];
    const float* b1     = (const float*)d_in[7];
    const float* g2     = (const float*)d_in[8];
    const float* mu2    = (const float*)d_in[9];
    const float* sigma2 = (const float*)d_in[10];
    const float* root2  = (const float*)d_in[11];
    const float* b2     = (const float*)d_in[12];
    const float* gs     = (const float*)d_in[13];
    const float* mus    = (const float*)d_in[14];
    const float* sigmas = (const float*)d_in[15];
    const float* roots  = (const float*)d_in[16];
    const float* bs     = (const float*)d_in[17];
    float* out = (float*)d_out;

    float *z1p, *z2p, *zsp, *hp, *r1p, *r2p;
    cudaGetSymbolAddress((void**)&z1p, d_z1);
    cudaGetSymbolAddress((void**)&z2p, d_z2);
    cudaGetSymbolAddress((void**)&zsp, d_zs);
    cudaGetSymbolAddress((void**)&hp,  d_h);
    cudaGetSymbolAddress((void**)&r1p, d_r1);
    cudaGetSymbolAddress((void**)&r2p, d_r2);

    const int MT = (N_NODES + 63) / 64;   // 641 row tiles

    // zero accumulators
    zero_bufs<<<(N_NODES * 128 + 255) / 256, 256>>>();

    // conv1: z1 = x@g1, r1 = x@root1
    gemm_tf32<<<dim3(640 / 64, MT), 256>>>(x, g1, z1p, N_NODES, 640, 0);
    gemm_tf32<<<dim3(1, MT), 256>>>(x, root1, r1p, N_NODES, 64, 0);
    edge_pass1<<<(N_EDGES * 32) / 256, 256>>>(ei, pseudo, mu1, sigma1);
    finish1<<<(N_NODES * 64 + 255) / 256, 256>>>(b1);

    // conv2 + shortcut
    gemm_tf32<<<dim3(1280 / 64, MT), 256>>>(hp, g2, z2p, N_NODES, 1280, 0);
    gemm_tf32<<<dim3(1280 / 64, MT), 256>>>(x, gs, zsp, N_NODES, 1280, 0);
    gemm_tf32<<<dim3(128 / 64, MT), 256>>>(hp, root2, r2p, N_NODES, 128, 0);
    gemm_tf32<<<dim3(128 / 64, MT), 256>>>(x, roots, r2p, N_NODES, 128, 1);
    edge_pass2<<<(N_EDGES * 32) / 256, 256>>>(ei, pseudo, mu2, sigma2, mus, sigmas);
    finish2<<<(N_NODES * 128 + 255) / 256, 256>>>(b2, bs, out);
}

// round 3
// speedup vs baseline: 1.8970x; 1.5292x over previous
#include <cuda_runtime.h>
#include <math.h>

#define N_NODES 40962
#define N_EDGES 245760
#define KG 10
#define GMM_EPS 1e-15f
#define K1 704      // 640 (t1) + 64 (x row, root1)
#define K2 1408     // 640 (t2) + 64 (h) + 640 (ts) + 64 (x)

// ---------------- scratch (device globals; no runtime allocation) -------------
__device__ int   d_cnt[N_NODES];
__device__ int   d_cur[N_NODES];
__device__ int   d_offs[N_NODES + 1];
__device__ float d_dinv[N_NODES];
__device__ int   d_ssrc[N_EDGES];
__device__ float d_wA[(size_t)N_EDGES * KG];        // conv1 weights, dst-sorted
__device__ float d_wB[(size_t)N_EDGES * 2 * KG];    // conv2 | shortcut weights
__device__ float d_t1[(size_t)N_NODES * K1];
__device__ float d_t2[(size_t)N_NODES * K2];
__device__ float d_h [(size_t)N_NODES * 64];
__device__ float d_B1[K1 * 64];
__device__ float d_B2[K2 * 128];
__device__ float d_bias2[128];

// ---------------- small prep kernels ------------------------------------------
__global__ void zero_cnt() {
    int i = blockIdx.x * blockDim.x + threadIdx.x;
    if (i < N_NODES) { d_cnt[i] = 0; d_cur[i] = 0; }
}

__global__ void hist_dst(const int* __restrict__ ei) {
    int e = blockIdx.x * blockDim.x + threadIdx.x;
    if (e < N_EDGES) atomicAdd(&d_cnt[ei[N_EDGES + e]], 1);
}

// single-block exclusive scan (warp-shuffle based), also writes 1/max(deg,1)
__global__ void scan_deg() {
    __shared__ int sh[32];
    __shared__ int carry;
    int t = threadIdx.x, lane = t & 31, wid = t >> 5;
    if (t == 0) { carry = 0; d_offs[0] = 0; }
    __syncthreads();
    for (int base = 0; base < N_NODES; base += 1024) {
        int i = base + t;
        int v = (i < N_NODES) ? d_cnt[i] : 0;
        if (i < N_NODES) d_dinv[i] = 1.0f / (float)max(v, 1);
        // warp inclusive scan
        int s = v;
        #pragma unroll
        for (int off = 1; off < 32; off <<= 1) {
            int n = __shfl_up_sync(0xffffffffu, s, off);
            if (lane >= off) s += n;
        }
        if (lane == 31) sh[wid] = s;
        __syncthreads();
        if (wid == 0) {
            int w = sh[lane];
            #pragma unroll
            for (int off = 1; off < 32; off <<= 1) {
                int n = __shfl_up_sync(0xffffffffu, w, off);
                if (lane >= off) w += n;
            }
            sh[lane] = w;
        }
        __syncthreads();
        int incl = s + (wid > 0 ? sh[wid - 1] : 0);
        int cbase = carry;
        if (i < N_NODES) d_offs[i + 1] = cbase + incl;
        __syncthreads();
        if (t == 1023) carry = cbase + incl;
        __syncthreads();
    }
}

// weave big B matrices: BigB1 = [G1'(640) ; root1(64)], BigB2 = [G2';root2;Gs';roots]
__global__ void bweave1(const float* __restrict__ g1, const float* __restrict__ root1) {
    int idx = blockIdx.x * blockDim.x + threadIdx.x;
    if (idx >= K1 * 64) return;
    int r = idx >> 6, c = idx & 63;
    float v;
    if (r < 640) { int k = r >> 6, cin = r & 63; v = g1[cin * 640 + k * 64 + c]; }
    else         { v = root1[(r - 640) * 64 + c]; }
    d_B1[idx] = v;
}

__global__ void bweave2(const float* __restrict__ g2, const float* __restrict__ root2,
                        const float* __restrict__ gs, const float* __restrict__ roots,
                        const float* __restrict__ b2, const float* __restrict__ bs) {
    int idx = blockIdx.x * blockDim.x + threadIdx.x;
    if (idx < 128) d_bias2[idx] = b2[idx] + bs[idx];
    if (idx >= K2 * 128) return;
    int r = idx >> 7, c = idx & 127;
    float v;
    if (r < 640)        { int k = r >> 6, cin = r & 63; v = g2[cin * 1280 + k * 128 + c]; }
    else if (r < 704)   { v = root2[(r - 640) * 128 + c]; }
    else if (r < 1344)  { int rr = r - 704; int k = rr >> 6, cin = rr & 63; v = gs[cin * 1280 + k * 128 + c]; }
    else                { v = roots[(r - 1344) * 128 + c]; }
    d_B2[idx] = v;
}

// ---------------- gaussian weights + dst-sort scatter -------------------------
__device__ __forceinline__ float gweight(float p0, float p1,
                                         const float* __restrict__ mu,
                                         const float* __restrict__ sg, int k) {
    float dx = p0 - mu[2 * k], dy = p1 - mu[2 * k + 1];
    float s0 = sg[2 * k],      s1 = sg[2 * k + 1];
    return __expf(-0.5f * dx * dx / (GMM_EPS + s0 * s0)
                  - 0.5f * dy * dy / (GMM_EPS + s1 * s1));
}

__global__ void scatterw(const int* __restrict__ ei, const float* __restrict__ pseudo,
                         const float* __restrict__ mu1, const float* __restrict__ sg1,
                         const float* __restrict__ mu2, const float* __restrict__ sg2,
                         const float* __restrict__ mus, const float* __restrict__ sgs) {
    int e = blockIdx.x * blockDim.x + threadIdx.x;
    if (e >= N_EDGES) return;
    int src = ei[e];
    int dst = ei[N_EDGES + e];
    float p0 = pseudo[2 * e], p1 = pseudo[2 * e + 1];
    int pos = d_offs[dst] + atomicAdd(&d_cur[dst], 1);
    d_ssrc[pos] = src;
    #pragma unroll
    for (int k = 0; k < KG; ++k) {
        d_wA[(size_t)pos * KG + k]          = gweight(p0, p1, mu1, sg1, k);
        d_wB[(size_t)pos * 2 * KG + k]      = gweight(p0, p1, mu2, sg2, k);
        d_wB[(size_t)pos * 2 * KG + KG + k] = gweight(p0, p1, mus, sgs, k);
    }
}

// ---------------- t-builds (warp per dst node, CSR) ---------------------------
__global__ __launch_bounds__(256) void tbuild1(const float* __restrict__ x) {
    int gw = (blockIdx.x * blockDim.x + threadIdx.x) >> 5;
    int lane = threadIdx.x & 31;
    if (gw >= N_NODES) return;
    int beg = d_offs[gw], end = d_offs[gw + 1];
    float dinv = d_dinv[gw];
    float a[KG][2];
    #pragma unroll
    for (int k = 0; k < KG; ++k) { a[k][0] = 0.f; a[k][1] = 0.f; }
    for (int e = beg; e < end; ++e) {
        int s = d_ssrc[e];
        float wv = (lane < KG) ? d_wA[(size_t)e * KG + lane] : 0.f;
        float x0 = x[(size_t)s * 64 + lane];
        float x1 = x[(size_t)s * 64 + 32 + lane];
        #pragma unroll
        for (int k = 0; k < KG; ++k) {
            float w = __shfl_sync(0xffffffffu, wv, k);
            a[k][0] = fmaf(w, x0, a[k][0]);
            a[k][1] = fmaf(w, x1, a[k][1]);
        }
    }
    float* tr = d_t1 + (size_t)gw * K1;
    #pragma unroll
    for (int k = 0; k < KG; ++k) {
        tr[k * 64 + lane]      = a[k][0] * dinv;
        tr[k * 64 + 32 + lane] = a[k][1] * dinv;
    }
    tr[640 + lane]      = x[(size_t)gw * 64 + lane];
    tr[640 + 32 + lane] = x[(size_t)gw * 64 + 32 + lane];
}

__global__ __launch_bounds__(256) void tbuild2(const float* __restrict__ x) {
    int gw = (blockIdx.x * blockDim.x + threadIdx.x) >> 5;
    int lane = threadIdx.x & 31;
    if (gw >= N_NODES) return;
    int beg = d_offs[gw], end = d_offs[gw + 1];
    float dinv = d_dinv[gw];
    float a2[KG][2], as_[KG][2];
    #pragma unroll
    for (int k = 0; k < KG; ++k) { a2[k][0]=0.f; a2[k][1]=0.f; as_[k][0]=0.f; as_[k][1]=0.f; }
    for (int e = beg; e < end; ++e) {
        int s = d_ssrc[e];
        float wv = (lane < 2 * KG) ? d_wB[(size_t)e * 2 * KG + lane] : 0.f;
        float h0 = d_h[(size_t)s * 64 + lane];
        float h1 = d_h[(size_t)s * 64 + 32 + lane];
        float x0 = x[(size_t)s * 64 + lane];
        float x1 = x[(size_t)s * 64 + 32 + lane];
        #pragma unroll
        for (int k = 0; k < KG; ++k) {
            float w2 = __shfl_sync(0xffffffffu, wv, k);
            float ws = __shfl_sync(0xffffffffu, wv, KG + k);
            a2[k][0]  = fmaf(w2, h0, a2[k][0]);
            a2[k][1]  = fmaf(w2, h1, a2[k][1]);
            as_[k][0] = fmaf(ws, x0, as_[k][0]);
            as_[k][1] = fmaf(ws, x1, as_[k][1]);
        }
    }
    float* tr = d_t2 + (size_t)gw * K2;
    #pragma unroll
    for (int k = 0; k < KG; ++k) {
        tr[k * 64 + lane]            = a2[k][0] * dinv;
        tr[k * 64 + 32 + lane]       = a2[k][1] * dinv;
        tr[704 + k * 64 + lane]      = as_[k][0] * dinv;
        tr[704 + k * 64 + 32 + lane] = as_[k][1] * dinv;
    }
    tr[640 + lane]       = d_h[(size_t)gw * 64 + lane];
    tr[640 + 32 + lane]  = d_h[(size_t)gw * 64 + 32 + lane];
    tr[1344 + lane]      = x[(size_t)gw * 64 + lane];
    tr[1344 + 32 + lane] = x[(size_t)gw * 64 + 32 + lane];
}

// ---------------- tf32 tensor-core GEMM with K loop, fused bias+relu ----------
// C[M,N] = relu(A[M,K] @ B[K,N] + bias),  lda=K, ldb=N, ldc=N. K % 64 == 0.
__device__ __forceinline__ unsigned f2tf32(float x) {
    unsigned r;
    asm("cvt.rna.tf32.f32 %0, %1;" : "=r"(r) : "f"(x));
    return r;
}
__device__ __forceinline__ unsigned fu(float x) { return __float_as_uint(x); }

__global__ __launch_bounds__(256) void gemm_big(
    const float* __restrict__ A, const float* __restrict__ B,
    float* __restrict__ C, int M, int N, int K, const float* __restrict__ bias)
{
    __shared__ float As[64][68];
    __shared__ float Bs[64][72];
    const int tid = threadIdx.x;
    const int bm = blockIdx.y * 64;
    const int bn = blockIdx.x * 64;

    const int wid = tid >> 5;
    const int l   = tid & 31;
    const int wr  = wid & 3;
    const int wc  = wid >> 2;
    const int tg  = l >> 2;
    const int ti  = l & 3;

    float acc[4][4] = {};

    for (int kc = 0; kc < K; kc += 64) {
        // load A tile
        {
            int row = tid >> 2;
            int cq  = (tid & 3) * 16;
            bool av = (bm + row) < M;
            const float* ap = A + (size_t)(bm + row) * K + kc + cq;
            #pragma unroll
            for (int j = 0; j < 4; ++j) {
                float4 v = av ? *(const float4*)(ap + 4 * j) : make_float4(0.f,0.f,0.f,0.f);
                As[row][cq + 4*j + 0] = __uint_as_float(f2tf32(v.x));
                As[row][cq + 4*j + 1] = __uint_as_float(f2tf32(v.y));
                As[row][cq + 4*j + 2] = __uint_as_float(f2tf32(v.z));
                As[row][cq + 4*j + 3] = __uint_as_float(f2tf32(v.w));
            }
        }
        // load B tile
        {
            int k  = tid >> 2;
            int nq = (tid & 3) * 16;
            const float* bp = B + (size_t)(kc + k) * N + bn + nq;
            #pragma unroll
            for (int j = 0; j < 4; ++j) {
                float4 v = *(const float4*)(bp + 4 * j);
                Bs[k][nq + 4*j + 0] = __uint_as_float(f2tf32(v.x));
                Bs[k][nq + 4*j + 1] = __uint_as_float(f2tf32(v.y));
                Bs[k][nq + 4*j + 2] = __uint_as_float(f2tf32(v.z));
                Bs[k][nq + 4*j + 3] = __uint_as_float(f2tf32(v.w));
            }
        }
        __syncthreads();

        #pragma unroll
        for (int ks = 0; ks < 8; ++ks) {
            int c0 = ks * 8 + ti;
            unsigned a0 = fu(As[wr * 16 + tg    ][c0    ]);
            unsigned a1 = fu(As[wr * 16 + tg + 8][c0    ]);
            unsigned a2 = fu(As[wr * 16 + tg    ][c0 + 4]);
            unsigned a3 = fu(As[wr * 16 + tg + 8][c0 + 4]);
            #pragma unroll
            for (int nt = 0; nt < 4; ++nt) {
                int bc = wc * 32 + nt * 8 + tg;
                unsigned b0 = fu(Bs[ks * 8 + ti    ][bc]);
                unsigned b1 = fu(Bs[ks * 8 + ti + 4][bc]);
                asm volatile(
                    "mma.sync.aligned.m16n8k8.row.col.f32.tf32.tf32.f32 "
                    "{%0,%1,%2,%3}, {%4,%5,%6,%7}, {%8,%9}, {%0,%1,%2,%3};"
                    : "+f"(acc[nt][0]), "+f"(acc[nt][1]),
                      "+f"(acc[nt][2]), "+f"(acc[nt][3])
                    : "r"(a0), "r"(a1), "r"(a2), "r"(a3), "r"(b0), "r"(b1));
            }
        }
        __syncthreads();
    }

    // epilogue: bias + relu
    #pragma unroll
    for (int nt = 0; nt < 4; ++nt) {
        int col = bn + wc * 32 + nt * 8 + 2 * ti;
        float bv0 = bias[col], bv1 = bias[col + 1];
        int r0 = bm + wr * 16 + tg;
        int r1 = r0 + 8;
        if (r0 < M) {
            float2 v = make_float2(fmaxf(acc[nt][0] + bv0, 0.f),
                                   fmaxf(acc[nt][1] + bv1, 0.f));
            *(float2*)(C + (size_t)r0 * N + col) = v;
        }
        if (r1 < M) {
            float2 v = make_float2(fmaxf(acc[nt][2] + bv0, 0.f),
                                   fmaxf(acc[nt][3] + bv1, 0.f));
            *(float2*)(C + (size_t)r1 * N + col) = v;
        }
    }
}

// ---------------- launch ------------------------------------------------------
extern "C" void kernel_launch(void* const* d_in, const int* in_sizes, int n_in,
                              void* d_out, int out_size) {
    const float* x      = (const float*)d_in[0];
    const int*   ei     = (const int*)  d_in[1];
    const float* pseudo = (const float*)d_in[2];
    const float* g1     = (const float*)d_in[3];
    const float* mu1    = (const float*)d_in[4];
    const float* sigma1 = (const float*)d_in[5];
    const float* root1  = (const float*)d_in[6];
    const float* b1     = (const float*)d_in[7];
    const float* g2     = (const float*)d_in[8];
    const float* mu2    = (const float*)d_in[9];
    const float* sigma2 = (const float*)d_in[10];
    const float* root2  = (const float*)d_in[11];
    const float* b2     = (const float*)d_in[12];
    const float* gs     = (const float*)d_in[13];
    const float* mus    = (const float*)d_in[14];
    const float* sigmas = (const float*)d_in[15];
    const float* roots  = (const float*)d_in[16];
    const float* bs     = (const float*)d_in[17];
    float* out = (float*)d_out;

    float *t1p, *t2p, *hp, *B1p, *B2p, *bias2p, *b1p;
    cudaGetSymbolAddress((void**)&t1p, d_t1);
    cudaGetSymbolAddress((void**)&t2p, d_t2);
    cudaGetSymbolAddress((void**)&hp,  d_h);
    cudaGetSymbolAddress((void**)&B1p, d_B1);
    cudaGetSymbolAddress((void**)&B2p, d_B2);
    cudaGetSymbolAddress((void**)&bias2p, d_bias2);
    b1p = (float*)b1;

    const int MT = (N_NODES + 63) / 64;        // 641 row tiles
    const int EW = (N_EDGES + 255) / 256;      // 960 edge blocks
    const int NW = (N_NODES * 32 + 255) / 256; // warp-per-node grid

    // CSR build
    zero_cnt<<<(N_NODES + 255) / 256, 256>>>();
    hist_dst<<<EW, 256>>>(ei);
    scan_deg<<<1, 1024>>>();
    bweave1<<<(K1 * 64 + 255) / 256, 256>>>(g1, root1);
    bweave2<<<(K2 * 128 + 255) / 256, 256>>>(g2, root2, gs, roots, b2, bs);
    scatterw<<<EW, 256>>>(ei, pseudo, mu1, sigma1, mu2, sigma2, mus, sigmas);

    // conv1: t1 = [mean-agg | x], h = relu(t1 @ B1 + b1)
    tbuild1<<<NW, 256>>>(x);
    gemm_big<<<dim3(1, MT), 256>>>(t1p, B1p, hp, N_NODES, 64, K1, b1p);

    // conv2 + shortcut fused: t2 = [agg2 | h | aggs | x], out = relu(t2 @ B2 + b2 + bs)
    tbuild2<<<NW, 256>>>(x);
    gemm_big<<<dim3(2, MT), 256>>>(t2p, B2p, out, N_NODES, 128, K2, bias2p);
}